// round 14
// baseline (speedup 1.0000x reference)
#include <cuda_runtime.h>

typedef unsigned long long ull;

#define HID 10
#define BATCH 16384
#define TPAIRS 1024
#define TPB 224
#define NBLK 148

// ---------- g_pack / c_w layout (250 longlong2), identical to r10-r13 ----------
#define OFF_WHB   0
#define OFF_WHA   100
#define OFF_WXB   200
#define OFF_WXA0  210
#define OFF_WXA1  220
#define OFF_BB    230
#define OFF_BA    240

__constant__ longlong2 c_w[250];
__device__   longlong2 g_pack[250];

// ---------- packed fp32x2 helpers ----------
__device__ __forceinline__ ull pack2(float lo, float hi){
    ull r; asm("mov.b64 %0, {%1, %2};" : "=l"(r) : "f"(lo), "f"(hi)); return r;
}
__device__ __forceinline__ ull bcast2(float v){
    ull r; asm("mov.b64 %0, {%1, %1};" : "=l"(r) : "f"(v)); return r;
}
__device__ __forceinline__ void unpack2(ull v, float &lo, float &hi){
    asm("mov.b64 {%0, %1}, %2;" : "=f"(lo), "=f"(hi) : "l"(v));
}
__device__ __forceinline__ ull ffma2(ull a, ull b, ull c){
    ull d; asm("fma.rn.f32x2 %0, %1, %2, %3;" : "=l"(d) : "l"(a), "l"(b), "l"(c)); return d;
}
__device__ __forceinline__ float tanh_ap(float x){
    float r; asm("tanh.approx.f32 %0, %1;" : "=f"(r) : "f"(x)); return r;
}

// ---------- pack kernel (identical to r10-r13, known-good) ----------
__global__ void pack_kernel(
    const float* __restrict__ WihA, const float* __restrict__ WhhA,
    const float* __restrict__ bihA, const float* __restrict__ bhhA,
    const float* __restrict__ WihB, const float* __restrict__ WhhB,
    const float* __restrict__ bihB, const float* __restrict__ bhhB)
{
    int idx = threadIdx.x;
    if (idx < 200){
        int cell = idx / 100;          // 0 = B, 1 = A
        int rem  = idx % 100;          // jj*10 + r*5 + p
        int jj = rem / 10;
        int r  = (rem % 10) / 5;
        int p  = rem % 5;
        int aj = (jj < 5) ? (5*r + jj) : (5*(1-r) + (jj-5));
        int d  = 5*r + p;
        const float* W = cell ? WhhA : WhhB;
        g_pack[(cell ? OFF_WHA : OFF_WHB) + rem] = make_longlong2(
            (long long)pack2(0.5f*W[(      d)*HID + aj], 0.5f*W[(  HID+d)*HID + aj]),
            (long long)pack2(     W[(2*HID+d)*HID + aj], 0.5f*W[(3*HID+d)*HID + aj]));
    } else if (idx < 250){
        int k = idx - 200;
        int grp = k / 10;              // 0 wxB, 1 wxA0, 2 wxA1, 3 bB, 4 bA
        int rp  = k % 10;              // r*5 + p
        int r = rp / 5, p = rp % 5;
        int d = 5*r + p;
        longlong2 v;
        if (grp == 0){
            v = make_longlong2(
                (long long)pack2(0.5f*WihB[d],         0.5f*WihB[HID+d]),
                (long long)pack2(     WihB[2*HID+d],   0.5f*WihB[3*HID+d]));
        } else if (grp == 1){
            v = make_longlong2(
                (long long)pack2(0.5f*WihA[(      d)*2], 0.5f*WihA[(  HID+d)*2]),
                (long long)pack2(     WihA[(2*HID+d)*2], 0.5f*WihA[(3*HID+d)*2]));
        } else if (grp == 2){
            v = make_longlong2(
                (long long)pack2(0.5f*WihA[(      d)*2+1], 0.5f*WihA[(  HID+d)*2+1]),
                (long long)pack2(     WihA[(2*HID+d)*2+1], 0.5f*WihA[(3*HID+d)*2+1]));
        } else if (grp == 3){
            v = make_longlong2(
                (long long)pack2(0.5f*(bihB[d]       + bhhB[d]),
                                 0.5f*(bihB[HID+d]   + bhhB[HID+d])),
                (long long)pack2(     (bihB[2*HID+d] + bhhB[2*HID+d]),
                                 0.5f*(bihB[3*HID+d] + bhhB[3*HID+d])));
        } else {
            v = make_longlong2(
                (long long)pack2(0.5f*(bihA[d]       + bhhA[d]),
                                 0.5f*(bihA[HID+d]   + bhhA[HID+d])),
                (long long)pack2(     (bihA[2*HID+d] + bhhA[2*HID+d]),
                                 0.5f*(bihA[3*HID+d] + bhhA[3*HID+d])));
        }
        g_pack[idx] = v;
    }
}

// ---------- cell step with persistent-hp (shfl overlapped into epilogue) ----------
// Invariant at entry: h[] = own dims, hp[] = partner dims (both current).
// Epilogue shfls each new h[p] immediately so the exchange latency hides
// under the remaining MUFU work instead of stalling the next cell's head.
template<int NIN>
__device__ __forceinline__ void cell_step(
    const longlong2* __restrict__ s_wh,
    const ull* w0if, const ull* w0go,     // own jj=0 row (registers)
    const ull* wx0if, const ull* wx0go,
    const ull* wx1if, const ull* wx1go,
    const ull* bif, const ull* bgo,
    int rbase, float h[5], float hp[5], float c[5], float x0, float x1)
{
    ull aIF[5], aGO[5];
#pragma unroll
    for (int p = 0; p < 5; p++){ aIF[p] = bif[p]; aGO[p] = bgo[p]; }

    // own jj=0 row from registers (no load)
    {
        ull hb = bcast2(h[0]);
#pragma unroll
        for (int p = 0; p < 5; p++){
            aIF[p] = ffma2(w0if[p], hb, aIF[p]);
            aGO[p] = ffma2(w0go[p], hb, aGO[p]);
        }
    }
    // smem own rows jj = 1..4
#pragma unroll
    for (int jj = 1; jj < 5; jj++){
        ull hb = bcast2(h[jj]);
#pragma unroll
        for (int p = 0; p < 5; p++){
            longlong2 w = s_wh[jj*10 + rbase + p];
            aIF[p] = ffma2((ull)w.x, hb, aIF[p]);
            aGO[p] = ffma2((ull)w.y, hb, aGO[p]);
        }
    }
    // smem partner rows jj = 5..9 (hp already resident — no shfl wait)
#pragma unroll
    for (int jj = 5; jj < 10; jj++){
        ull hb = bcast2(hp[jj-5]);
#pragma unroll
        for (int p = 0; p < 5; p++){
            longlong2 w = s_wh[jj*10 + rbase + p];
            aIF[p] = ffma2((ull)w.x, hb, aIF[p]);
            aGO[p] = ffma2((ull)w.y, hb, aGO[p]);
        }
    }
    // x contributions LAST: matvec above covers the x LDG latency
    {
        ull xb = bcast2(x0);
#pragma unroll
        for (int p = 0; p < 5; p++){
            aIF[p] = ffma2(wx0if[p], xb, aIF[p]);
            aGO[p] = ffma2(wx0go[p], xb, aGO[p]);
        }
    }
    if (NIN == 2){
        ull xb = bcast2(x1);
#pragma unroll
        for (int p = 0; p < 5; p++){
            aIF[p] = ffma2(wx1if[p], xb, aIF[p]);
            aGO[p] = ffma2(wx1go[p], xb, aGO[p]);
        }
    }
    // epilogue: 5 MUFU per owned dim; shfl each h[p] as soon as it exists
#pragma unroll
    for (int p = 0; p < 5; p++){
        float zi, zf, zg, zo;
        unpack2(aIF[p], zi, zf);
        unpack2(aGO[p], zg, zo);
        float si = fmaf(0.5f, tanh_ap(zi), 0.5f);
        float sf = fmaf(0.5f, tanh_ap(zf), 0.5f);
        float tg = tanh_ap(zg);
        float so = fmaf(0.5f, tanh_ap(zo), 0.5f);
        float cn = fmaf(sf, c[p], si * tg);
        c[p] = cn;
        float hn = so * tanh_ap(cn);
        h[p]  = hn;
        hp[p] = __shfl_xor_sync(0xffffffffu, hn, 1);  // overlapped exchange
    }
}

__global__ void __launch_bounds__(TPB, 1)
multicell_lstm_kernel(
    const float* __restrict__ x,
    const float* __restrict__ Wlin, const float* __restrict__ blin,
    float* __restrict__ out)
{
    // all recurrent weights in smem: [0..99] whB, [100..199] whA
    __shared__ longlong2 s_w[200];
    const int tid = threadIdx.x;
    for (int i = tid; i < 200; i += TPB) s_w[i] = g_pack[i];
    __syncthreads();

    // element id; activity boundary is warp-uniform (148*224 vs 2*16384)
    const int e = (blockIdx.x * TPB + tid) >> 1;
    if (e >= BATCH) return;

    const int rbase = (tid & 1) * 5;

    // one-time divergent const reads -> registers (loop-invariant)
    ull bBif[5], bBgo[5], bAif[5], bAgo[5];
    ull wxBif[5], wxBgo[5], wxA0if[5], wxA0go[5], wxA1if[5], wxA1go[5];
    ull wA0if[5], wA0go[5];   // whA jj=0 own-row slice
    ull wB0if[5], wB0go[5];   // whB jj=0 own-row slice
#pragma unroll
    for (int p = 0; p < 5; p++){
        longlong2 vb   = c_w[OFF_BB   + rbase + p];
        longlong2 va   = c_w[OFF_BA   + rbase + p];
        longlong2 vxb  = c_w[OFF_WXB  + rbase + p];
        longlong2 vxa0 = c_w[OFF_WXA0 + rbase + p];
        longlong2 vxa1 = c_w[OFF_WXA1 + rbase + p];
        longlong2 vwa0 = c_w[OFF_WHA  + rbase + p];
        longlong2 vwb0 = c_w[OFF_WHB  + rbase + p];
        bBif[p]   = (ull)vb.x;   bBgo[p]   = (ull)vb.y;
        bAif[p]   = (ull)va.x;   bAgo[p]   = (ull)va.y;
        wxBif[p]  = (ull)vxb.x;  wxBgo[p]  = (ull)vxb.y;
        wxA0if[p] = (ull)vxa0.x; wxA0go[p] = (ull)vxa0.y;
        wxA1if[p] = (ull)vxa1.x; wxA1go[p] = (ull)vxa1.y;
        wA0if[p]  = (ull)vwa0.x; wA0go[p]  = (ull)vwa0.y;
        wB0if[p]  = (ull)vwb0.x; wB0go[p]  = (ull)vwb0.y;
    }

    const float4* xp = reinterpret_cast<const float4*>(x) + (size_t)e * TPAIRS;

    float h[5], hp[5], c[5];
#pragma unroll
    for (int p = 0; p < 5; p++){ h[p] = 0.0f; hp[p] = 0.0f; c[p] = 0.0f; }

    // 2x-unrolled pair loop with software prefetch (distance 1)
    float4 xv0 = __ldg(&xp[0]);
    for (int p = 0; p < TPAIRS; p += 2){
        float4 xv1 = __ldg(&xp[p + 1]);
        cell_step<1>(s_w,       wB0if, wB0go, wxBif,  wxBgo,  wxBif,  wxBgo,
                     bBif, bBgo, rbase, h, hp, c, xv0.x, 0.0f);
        cell_step<2>(s_w + 100, wA0if, wA0go, wxA0if, wxA0go, wxA1if, wxA1go,
                     bAif, bAgo, rbase, h, hp, c, xv0.z, xv0.w);
        float4 xvn = __ldg(&xp[(p + 2) & (TPAIRS - 1)]);   // wrap: harmless reload
        cell_step<1>(s_w,       wB0if, wB0go, wxBif,  wxBgo,  wxBif,  wxBgo,
                     bBif, bBgo, rbase, h, hp, c, xv1.x, 0.0f);
        cell_step<2>(s_w + 100, wA0if, wA0go, wxA0if, wxA0go, wxA1if, wxA1go,
                     bAif, bAgo, rbase, h, hp, c, xv1.z, xv1.w);
        xv0 = xvn;
    }

    // out = sigmoid(h @ Wlin.T + blin): partial dot over owned dims + pair-sum
    float a = 0.0f;
#pragma unroll
    for (int p = 0; p < 5; p++) a = fmaf(h[p], __ldg(&Wlin[rbase + p]), a);
    a += __shfl_xor_sync(0xffffffffu, a, 1);
    if ((tid & 1) == 0)
        out[e] = fmaf(0.5f, tanh_ap(0.5f * (a + __ldg(&blin[0]))), 0.5f);
}

extern "C" void kernel_launch(void* const* d_in, const int* in_sizes, int n_in,
                              void* d_out, int out_size)
{
    const float* x    = (const float*)d_in[0];
    const float* WihA = (const float*)d_in[1];
    const float* WhhA = (const float*)d_in[2];
    const float* bihA = (const float*)d_in[3];
    const float* bhhA = (const float*)d_in[4];
    const float* WihB = (const float*)d_in[5];
    const float* WhhB = (const float*)d_in[6];
    const float* bihB = (const float*)d_in[7];
    const float* bhhB = (const float*)d_in[8];
    const float* Wlin = (const float*)d_in[9];
    const float* blin = (const float*)d_in[10];
    float* out = (float*)d_out;

    pack_kernel<<<1, 256>>>(WihA, WhhA, bihA, bhhA, WihB, WhhB, bihB, bhhB);

    void* g_pack_dev = nullptr;
    cudaGetSymbolAddress(&g_pack_dev, g_pack);
    cudaMemcpyToSymbolAsync(c_w, g_pack_dev, 250 * sizeof(longlong2), 0,
                            cudaMemcpyDeviceToDevice, 0);

    // 148 x 224; persistent-hp (shfl overlapped) + 2x-unrolled loop
    dim3 grid(NBLK), block(TPB);
    multicell_lstm_kernel<<<grid, block>>>(x, Wlin, blin, out);
}

// round 15
// speedup vs baseline: 2.5970x; 2.5970x over previous
#include <cuda_runtime.h>

typedef unsigned long long ull;

#define HID 10
#define BATCH 16384
#define TPAIRS 1024
#define TPB 224
#define NBLK 148

// ---------- g_pack / c_w layout (250 longlong2), identical to r10-r13 ----------
#define OFF_WHB   0
#define OFF_WHA   100
#define OFF_WXB   200
#define OFF_WXA0  210
#define OFF_WXA1  220
#define OFF_BB    230
#define OFF_BA    240

__constant__ longlong2 c_w[250];
__device__   longlong2 g_pack[250];

// ---------- packed fp32x2 helpers ----------
__device__ __forceinline__ ull pack2(float lo, float hi){
    ull r; asm("mov.b64 %0, {%1, %2};" : "=l"(r) : "f"(lo), "f"(hi)); return r;
}
__device__ __forceinline__ ull bcast2(float v){
    ull r; asm("mov.b64 %0, {%1, %1};" : "=l"(r) : "f"(v)); return r;
}
__device__ __forceinline__ void unpack2(ull v, float &lo, float &hi){
    asm("mov.b64 {%0, %1}, %2;" : "=f"(lo), "=f"(hi) : "l"(v));
}
__device__ __forceinline__ ull ffma2(ull a, ull b, ull c){
    ull d; asm("fma.rn.f32x2 %0, %1, %2, %3;" : "=l"(d) : "l"(a), "l"(b), "l"(c)); return d;
}
__device__ __forceinline__ float tanh_ap(float x){
    float r; asm("tanh.approx.f32 %0, %1;" : "=f"(r) : "f"(x)); return r;
}

// ---------- pack kernel (identical to r10-r13, known-good) ----------
__global__ void pack_kernel(
    const float* __restrict__ WihA, const float* __restrict__ WhhA,
    const float* __restrict__ bihA, const float* __restrict__ bhhA,
    const float* __restrict__ WihB, const float* __restrict__ WhhB,
    const float* __restrict__ bihB, const float* __restrict__ bhhB)
{
    int idx = threadIdx.x;
    if (idx < 200){
        int cell = idx / 100;          // 0 = B, 1 = A
        int rem  = idx % 100;          // jj*10 + r*5 + p
        int jj = rem / 10;
        int r  = (rem % 10) / 5;
        int p  = rem % 5;
        int aj = (jj < 5) ? (5*r + jj) : (5*(1-r) + (jj-5));
        int d  = 5*r + p;
        const float* W = cell ? WhhA : WhhB;
        g_pack[(cell ? OFF_WHA : OFF_WHB) + rem] = make_longlong2(
            (long long)pack2(0.5f*W[(      d)*HID + aj], 0.5f*W[(  HID+d)*HID + aj]),
            (long long)pack2(     W[(2*HID+d)*HID + aj], 0.5f*W[(3*HID+d)*HID + aj]));
    } else if (idx < 250){
        int k = idx - 200;
        int grp = k / 10;              // 0 wxB, 1 wxA0, 2 wxA1, 3 bB, 4 bA
        int rp  = k % 10;              // r*5 + p
        int r = rp / 5, p = rp % 5;
        int d = 5*r + p;
        longlong2 v;
        if (grp == 0){
            v = make_longlong2(
                (long long)pack2(0.5f*WihB[d],         0.5f*WihB[HID+d]),
                (long long)pack2(     WihB[2*HID+d],   0.5f*WihB[3*HID+d]));
        } else if (grp == 1){
            v = make_longlong2(
                (long long)pack2(0.5f*WihA[(      d)*2], 0.5f*WihA[(  HID+d)*2]),
                (long long)pack2(     WihA[(2*HID+d)*2], 0.5f*WihA[(3*HID+d)*2]));
        } else if (grp == 2){
            v = make_longlong2(
                (long long)pack2(0.5f*WihA[(      d)*2+1], 0.5f*WihA[(  HID+d)*2+1]),
                (long long)pack2(     WihA[(2*HID+d)*2+1], 0.5f*WihA[(3*HID+d)*2+1]));
        } else if (grp == 3){
            v = make_longlong2(
                (long long)pack2(0.5f*(bihB[d]       + bhhB[d]),
                                 0.5f*(bihB[HID+d]   + bhhB[HID+d])),
                (long long)pack2(     (bihB[2*HID+d] + bhhB[2*HID+d]),
                                 0.5f*(bihB[3*HID+d] + bhhB[3*HID+d])));
        } else {
            v = make_longlong2(
                (long long)pack2(0.5f*(bihA[d]       + bhhA[d]),
                                 0.5f*(bihA[HID+d]   + bhhA[HID+d])),
                (long long)pack2(     (bihA[2*HID+d] + bhhA[2*HID+d]),
                                 0.5f*(bihA[3*HID+d] + bhhA[3*HID+d])));
        }
        g_pack[idx] = v;
    }
}

// ---------- cell step, persistent-hp, optional register jj=0 row ----------
// Invariant at entry: h[] own dims, hp[] partner dims, both current.
// Epilogue shfls each new h[p] immediately -> exchange hidden under MUFUs.
template<int NIN, bool R0REG>
__device__ __forceinline__ void cell_step(
    const longlong2* __restrict__ s_wh,
    const ull* w0if, const ull* w0go,     // own jj=0 row (used iff R0REG)
    const ull* wx0if, const ull* wx0go,
    const ull* wx1if, const ull* wx1go,
    const ull* bif, const ull* bgo,
    int rbase, float h[5], float hp[5], float c[5], float x0, float x1)
{
    ull aIF[5], aGO[5];
#pragma unroll
    for (int p = 0; p < 5; p++){ aIF[p] = bif[p]; aGO[p] = bgo[p]; }

    // own jj=0 row: registers (cell A) or smem (cell B)
    if (R0REG){
        ull hb = bcast2(h[0]);
#pragma unroll
        for (int p = 0; p < 5; p++){
            aIF[p] = ffma2(w0if[p], hb, aIF[p]);
            aGO[p] = ffma2(w0go[p], hb, aGO[p]);
        }
    } else {
        ull hb = bcast2(h[0]);
#pragma unroll
        for (int p = 0; p < 5; p++){
            longlong2 w = s_wh[rbase + p];
            aIF[p] = ffma2((ull)w.x, hb, aIF[p]);
            aGO[p] = ffma2((ull)w.y, hb, aGO[p]);
        }
    }
    // smem own rows jj = 1..4
#pragma unroll
    for (int jj = 1; jj < 5; jj++){
        ull hb = bcast2(h[jj]);
#pragma unroll
        for (int p = 0; p < 5; p++){
            longlong2 w = s_wh[jj*10 + rbase + p];
            aIF[p] = ffma2((ull)w.x, hb, aIF[p]);
            aGO[p] = ffma2((ull)w.y, hb, aGO[p]);
        }
    }
    // smem partner rows jj = 5..9 (hp already resident — no shfl wait)
#pragma unroll
    for (int jj = 5; jj < 10; jj++){
        ull hb = bcast2(hp[jj-5]);
#pragma unroll
        for (int p = 0; p < 5; p++){
            longlong2 w = s_wh[jj*10 + rbase + p];
            aIF[p] = ffma2((ull)w.x, hb, aIF[p]);
            aGO[p] = ffma2((ull)w.y, hb, aGO[p]);
        }
    }
    // x contributions LAST: matvec above covers the x LDG latency
    {
        ull xb = bcast2(x0);
#pragma unroll
        for (int p = 0; p < 5; p++){
            aIF[p] = ffma2(wx0if[p], xb, aIF[p]);
            aGO[p] = ffma2(wx0go[p], xb, aGO[p]);
        }
    }
    if (NIN == 2){
        ull xb = bcast2(x1);
#pragma unroll
        for (int p = 0; p < 5; p++){
            aIF[p] = ffma2(wx1if[p], xb, aIF[p]);
            aGO[p] = ffma2(wx1go[p], xb, aGO[p]);
        }
    }
    // epilogue: 5 MUFU per owned dim; shfl each h[p] as soon as it exists
#pragma unroll
    for (int p = 0; p < 5; p++){
        float zi, zf, zg, zo;
        unpack2(aIF[p], zi, zf);
        unpack2(aGO[p], zg, zo);
        float si = fmaf(0.5f, tanh_ap(zi), 0.5f);
        float sf = fmaf(0.5f, tanh_ap(zf), 0.5f);
        float tg = tanh_ap(zg);
        float so = fmaf(0.5f, tanh_ap(zo), 0.5f);
        float cn = fmaf(sf, c[p], si * tg);
        c[p] = cn;
        float hn = so * tanh_ap(cn);
        h[p]  = hn;
        hp[p] = __shfl_xor_sync(0xffffffffu, hn, 1);  // overlapped exchange
    }
}

__global__ void __launch_bounds__(TPB, 1)
multicell_lstm_kernel(
    const float* __restrict__ x,
    const float* __restrict__ Wlin, const float* __restrict__ blin,
    float* __restrict__ out)
{
    // all recurrent weights in smem: [0..99] whB, [100..199] whA
    __shared__ longlong2 s_w[200];
    const int tid = threadIdx.x;
    for (int i = tid; i < 200; i += TPB) s_w[i] = g_pack[i];
    __syncthreads();

    // element id; activity boundary is warp-uniform (148*224 vs 2*16384)
    const int e = (blockIdx.x * TPB + tid) >> 1;
    if (e >= BATCH) return;

    const int rbase = (tid & 1) * 5;

    // one-time divergent const reads -> registers (loop-invariant)
    ull bBif[5], bBgo[5], bAif[5], bAgo[5];
    ull wxBif[5], wxBgo[5], wxA0if[5], wxA0go[5], wxA1if[5], wxA1go[5];
    ull wA0if[5], wA0go[5];   // whA jj=0 own-row slice (cell A only; B row stays in smem)
#pragma unroll
    for (int p = 0; p < 5; p++){
        longlong2 vb   = c_w[OFF_BB   + rbase + p];
        longlong2 va   = c_w[OFF_BA   + rbase + p];
        longlong2 vxb  = c_w[OFF_WXB  + rbase + p];
        longlong2 vxa0 = c_w[OFF_WXA0 + rbase + p];
        longlong2 vxa1 = c_w[OFF_WXA1 + rbase + p];
        longlong2 vwa0 = c_w[OFF_WHA  + rbase + p];
        bBif[p]   = (ull)vb.x;   bBgo[p]   = (ull)vb.y;
        bAif[p]   = (ull)va.x;   bAgo[p]   = (ull)va.y;
        wxBif[p]  = (ull)vxb.x;  wxBgo[p]  = (ull)vxb.y;
        wxA0if[p] = (ull)vxa0.x; wxA0go[p] = (ull)vxa0.y;
        wxA1if[p] = (ull)vxa1.x; wxA1go[p] = (ull)vxa1.y;
        wA0if[p]  = (ull)vwa0.x; wA0go[p]  = (ull)vwa0.y;
    }

    const float4* xp = reinterpret_cast<const float4*>(x) + (size_t)e * TPAIRS;

    float h[5], hp[5], c[5];
#pragma unroll
    for (int p = 0; p < 5; p++){ h[p] = 0.0f; hp[p] = 0.0f; c[p] = 0.0f; }

    // software prefetch (distance 1), no unroll (register budget!)
    float4 xv = __ldg(&xp[0]);
    for (int p = 0; p < TPAIRS; p++){
        float4 xnext = __ldg(&xp[(p + 1) & (TPAIRS - 1)]);
        cell_step<1, false>(s_w,       wA0if, wA0go, wxBif,  wxBgo,  wxBif,  wxBgo,
                            bBif, bBgo, rbase, h, hp, c, xv.x, 0.0f);
        cell_step<2, true >(s_w + 100, wA0if, wA0go, wxA0if, wxA0go, wxA1if, wxA1go,
                            bAif, bAgo, rbase, h, hp, c, xv.z, xv.w);
        xv = xnext;
    }

    // out = sigmoid(h @ Wlin.T + blin): partial dot over owned dims + pair-sum
    float a = 0.0f;
#pragma unroll
    for (int p = 0; p < 5; p++) a = fmaf(h[p], __ldg(&Wlin[rbase + p]), a);
    a += __shfl_xor_sync(0xffffffffu, a, 1);
    if ((tid & 1) == 0)
        out[e] = fmaf(0.5f, tanh_ap(0.5f * (a + __ldg(&blin[0]))), 0.5f);
}

extern "C" void kernel_launch(void* const* d_in, const int* in_sizes, int n_in,
                              void* d_out, int out_size)
{
    const float* x    = (const float*)d_in[0];
    const float* WihA = (const float*)d_in[1];
    const float* WhhA = (const float*)d_in[2];
    const float* bihA = (const float*)d_in[3];
    const float* bhhA = (const float*)d_in[4];
    const float* WihB = (const float*)d_in[5];
    const float* WhhB = (const float*)d_in[6];
    const float* bihB = (const float*)d_in[7];
    const float* bhhB = (const float*)d_in[8];
    const float* Wlin = (const float*)d_in[9];
    const float* blin = (const float*)d_in[10];
    float* out = (float*)d_out;

    pack_kernel<<<1, 256>>>(WihA, WhhA, bihA, bhhA, WihB, WhhB, bihB, bhhB);

    void* g_pack_dev = nullptr;
    cudaGetSymbolAddress(&g_pack_dev, g_pack);
    cudaMemcpyToSymbolAsync(c_w, g_pack_dev, 250 * sizeof(longlong2), 0,
                            cudaMemcpyDeviceToDevice, 0);

    // 148 x 224; persistent-hp (shfl in epilogue), no unroll,
    // wB0 row back in smem to fund the +5 live regs (target ~237 regs)
    dim3 grid(NBLK), block(TPB);
    multicell_lstm_kernel<<<grid, block>>>(x, Wlin, blin, out);
}